// round 1
// baseline (speedup 1.0000x reference)
#include <cuda_runtime.h>
#include <math.h>

#define BB 16
#define NN 128
#define HH 64
#define NEGS 0.01f
// f32(0.4*0.4 computed in double) — matches jnp weak-type cast of the python scalar
#define DRN2 0.16000000000000003f
// 2.0 * np.float32(np.pi), exact
#define TWO_PI 6.2831854820251465f

// Scratch (no allocations allowed in kernel_launch)
__device__ float g_f1[BB * NN * HH];     // layer-1 output features
__device__ float g_a1[BB * NN * 2];      // rotated coords after layer 1
__device__ float g_u2[BB * NN * HH];     // per-node u for layer 2
__device__ float g_v2[BB * NN * HH];     // per-node v for layer 2
__device__ float g_feat2[BB * NN * 66];  // [agg_m2[:64], rot2] per node

// ---------------------------------------------------------------------------
// Layer 1: Df = 1 (feature = r). Fully fused per (b, i) block.
// ---------------------------------------------------------------------------
__global__ void __launch_bounds__(64) k_layer1(
    const float* __restrict__ pt, const float* __restrict__ ang,
    const float* __restrict__ W00, const float* __restrict__ b00,
    const float* __restrict__ W01, const float* __restrict__ b01) {
  int b = blockIdx.y, i = blockIdx.x, t = threadIdx.x;
  __shared__ float ax[NN], ay[NN], rr[NN], cs[NN], sn[NN], wj[NN], hsm[HH];
  __shared__ float red[2];

  for (int j = t; j < NN; j += 64) {
    float x = ang[(b * NN + j) * 2 + 0];
    float y = ang[(b * NN + j) * 2 + 1];
    ax[j] = x; ay[j] = y;
    rr[j] = sqrtf(x * x + y * y);
  }
  __syncthreads();

  float xi = ax[i], yi = ay[i];
  float r2i = xi * xi + yi * yi;

  float padj = 0.f;
  for (int j = t; j < NN; j += 64) {
    float xj = ax[j], yj = ay[j];
    float dx = xi - xj, dy = yi - yj;
    float d2 = dx * dx + dy * dy;
    float adj = (d2 <= DRN2) ? 1.f : 0.f;
    padj += adj;
    float r2j = xj * xj + yj * yj;
    float inv = rsqrtf(r2i * r2j);
    cs[j] = (xi * xj + yi * yj) * inv;
    sn[j] = (yi * xj - xi * yj) * inv;
    wj[j] = adj;  // scaled below
  }
  for (int o = 16; o; o >>= 1) padj += __shfl_down_sync(0xffffffffu, padj, o);
  if ((t & 31) == 0) red[t >> 5] = padj;
  __syncthreads();
  float invdeg = 1.f / (red[0] + red[1]);
  for (int j = t; j < NN; j += 64) wj[j] *= invdeg;
  __syncthreads();

  // z_ij[h] = u + r_j*vc + cos*wc + sin*ws ; h_i[h] = sum_j wj * leaky(z)
  int h = t;
  float ri = rr[i];
  float u  = ri * (W00[h] - W00[128 + h]) + b00[h];
  float vc = W00[64 + h] + W00[128 + h];
  float wc = W00[192 + h], ws = W00[256 + h];
  float acc = 0.f;
#pragma unroll 4
  for (int j = 0; j < NN; ++j) {
    float z = u + rr[j] * vc + cs[j] * wc + sn[j] * ws;
    float zl = (z >= 0.f) ? z : NEGS * z;
    acc += wj[j] * zl;
  }
  hsm[h] = acc;
  __syncthreads();

  // agg_m = h @ W01 + b01 (65 outputs); f1 = agg_m[:64], gamma = agg_m[64]
  float dot = b01[h];
#pragma unroll 8
  for (int k = 0; k < HH; ++k) dot += hsm[k] * W01[k * 65 + h];
  g_f1[(b * NN + i) * HH + h] = dot;

  if (t == 0) {
    float gam = b01[64];
    for (int k = 0; k < HH; ++k) gam += hsm[k] * W01[k * 65 + 64];
    float a2 = TWO_PI * gam;
    float co = cosf(a2), si = sinf(a2);
    g_a1[(b * NN + i) * 2 + 0] = co * xi - si * yi;
    g_a1[(b * NN + i) * 2 + 1] = si * xi + co * yi;
  }
}

// ---------------------------------------------------------------------------
// Precompute u2 = f1@(W10[0:64]-W10[128:192]) + b10, v2 = f1@(W10[64:128]+W10[128:192])
// ---------------------------------------------------------------------------
__global__ void __launch_bounds__(64) k_uv(
    const float* __restrict__ W10, const float* __restrict__ b10) {
  int b = blockIdx.y, i = blockIdx.x, h = threadIdx.x;
  __shared__ float fs[HH];
  fs[h] = g_f1[(b * NN + i) * HH + h];
  __syncthreads();
  float u = b10[h], v = 0.f;
#pragma unroll 4
  for (int d = 0; d < HH; ++d) {
    float fd = fs[d];
    float wa = W10[d * HH + h];
    float wb = W10[(64 + d) * HH + h];
    float wd = W10[(128 + d) * HH + h];
    u += fd * (wa - wd);
    v += fd * (wb + wd);
  }
  g_u2[(b * NN + i) * HH + h] = u;
  g_v2[(b * NN + i) * HH + h] = v;
}

// ---------------------------------------------------------------------------
// Layer 2: Df = 64, using precomputed u2/v2.
// ---------------------------------------------------------------------------
__global__ void __launch_bounds__(64) k_layer2(
    const float* __restrict__ W10, const float* __restrict__ W11,
    const float* __restrict__ b11) {
  int b = blockIdx.y, i = blockIdx.x, t = threadIdx.x;
  __shared__ float ax[NN], ay[NN], cs[NN], sn[NN], wj[NN], hsm[HH];
  __shared__ float red[2];

  for (int j = t; j < NN; j += 64) {
    ax[j] = g_a1[(b * NN + j) * 2 + 0];
    ay[j] = g_a1[(b * NN + j) * 2 + 1];
  }
  __syncthreads();

  float xi = ax[i], yi = ay[i];
  float r2i = xi * xi + yi * yi;

  float padj = 0.f;
  for (int j = t; j < NN; j += 64) {
    float xj = ax[j], yj = ay[j];
    float dx = xi - xj, dy = yi - yj;
    float d2 = dx * dx + dy * dy;
    float adj = (d2 <= DRN2) ? 1.f : 0.f;
    padj += adj;
    float r2j = xj * xj + yj * yj;
    float inv = rsqrtf(r2i * r2j);
    cs[j] = (xi * xj + yi * yj) * inv;
    sn[j] = (yi * xj - xi * yj) * inv;
    wj[j] = adj;
  }
  for (int o = 16; o; o >>= 1) padj += __shfl_down_sync(0xffffffffu, padj, o);
  if ((t & 31) == 0) red[t >> 5] = padj;
  __syncthreads();
  float invdeg = 1.f / (red[0] + red[1]);
  for (int j = t; j < NN; j += 64) wj[j] *= invdeg;
  __syncthreads();

  int h = t;
  float u  = g_u2[(b * NN + i) * HH + h];
  float wc = W10[192 * HH + h], ws = W10[193 * HH + h];
  const float* vrow = g_v2 + (size_t)b * NN * HH + h;
  float acc = 0.f;
#pragma unroll 4
  for (int j = 0; j < NN; ++j) {
    float z = u + vrow[j * HH] + cs[j] * wc + sn[j] * ws;
    float zl = (z >= 0.f) ? z : NEGS * z;
    acc += wj[j] * zl;
  }
  hsm[h] = acc;
  __syncthreads();

  float dot = b11[h];
#pragma unroll 8
  for (int k = 0; k < HH; ++k) dot += hsm[k] * W11[k * 65 + h];
  g_feat2[(b * NN + i) * 66 + h] = dot;

  if (t == 0) {
    float gam = b11[64];
    for (int k = 0; k < HH; ++k) gam += hsm[k] * W11[k * 65 + 64];
    float a2 = TWO_PI * gam;
    float co = cosf(a2), si = sinf(a2);
    g_feat2[(b * NN + i) * 66 + 64] = co * xi - si * yi;
    g_feat2[(b * NN + i) * 66 + 65] = si * xi + co * yi;
  }
}

// ---------------------------------------------------------------------------
// Readout: g = sum_n (pt_n/sum pt) * feat2[n]; tiny MLP 64->32->32->1.
// ---------------------------------------------------------------------------
__global__ void __launch_bounds__(128) k_readout(
    const float* __restrict__ pt,
    const float* __restrict__ Wr0, const float* __restrict__ br0,
    const float* __restrict__ Wr1, const float* __restrict__ br1,
    const float* __restrict__ Wr2, const float* __restrict__ br2,
    float* __restrict__ out) {
  int b = blockIdx.x, t = threadIdx.x;
  __shared__ float ptn[NN], g[66], h1[32], h2[32];
  __shared__ float red[4];

  ptn[t] = pt[b * NN + t];
  __syncthreads();
  float s = ptn[t];
  for (int o = 16; o; o >>= 1) s += __shfl_down_sync(0xffffffffu, s, o);
  if ((t & 31) == 0) red[t >> 5] = s;
  __syncthreads();
  float invs = 1.f / (red[0] + red[1] + red[2] + red[3]);

  if (t < 66) {
    float acc = 0.f;
    for (int n = 0; n < NN; ++n) acc += ptn[n] * g_feat2[(b * NN + n) * 66 + t];
    g[t] = acc * invs;
  }
  __syncthreads();

  if (t < 32) {
    float z = br0[t];
#pragma unroll 8
    for (int d = 0; d < 64; ++d) z += g[d] * Wr0[d * 32 + t];
    h1[t] = (z >= 0.f) ? z : NEGS * z;
  }
  __syncthreads();
  if (t < 32) {
    float z = br1[t];
#pragma unroll 8
    for (int d = 0; d < 32; ++d) z += h1[d] * Wr1[d * 32 + t];
    h2[t] = (z >= 0.f) ? z : NEGS * z;
  }
  __syncthreads();
  if (t == 0) {
    float z = br2[0];
    for (int d = 0; d < 32; ++d) z += h2[d] * Wr2[d];
    out[b * 3 + 0] = 1.f / (1.f + expf(-z));
    out[b * 3 + 1] = g[64];
    out[b * 3 + 2] = g[65];
  }
}

extern "C" void kernel_launch(void* const* d_in, const int* in_sizes, int n_in,
                              void* d_out, int out_size) {
  const float* pt  = (const float*)d_in[0];
  const float* ang = (const float*)d_in[1];
  const float* W00 = (const float*)d_in[2];
  const float* b00 = (const float*)d_in[3];
  const float* W01 = (const float*)d_in[4];
  const float* b01 = (const float*)d_in[5];
  const float* W10 = (const float*)d_in[6];
  const float* b10 = (const float*)d_in[7];
  const float* W11 = (const float*)d_in[8];
  const float* b11 = (const float*)d_in[9];
  const float* Wr0 = (const float*)d_in[10];
  const float* br0 = (const float*)d_in[11];
  const float* Wr1 = (const float*)d_in[12];
  const float* br1 = (const float*)d_in[13];
  const float* Wr2 = (const float*)d_in[14];
  const float* br2 = (const float*)d_in[15];
  float* out = (float*)d_out;

  dim3 grid(NN, BB);
  k_layer1<<<grid, 64>>>(pt, ang, W00, b00, W01, b01);
  k_uv<<<grid, 64>>>(W10, b10);
  k_layer2<<<grid, 64>>>(W10, W11, b11);
  k_readout<<<BB, 128>>>(pt, Wr0, br0, Wr1, br1, Wr2, br2, out);
}

// round 2
// speedup vs baseline: 1.1145x; 1.1145x over previous
#include <cuda_runtime.h>
#include <math.h>

#define BB 16
#define NN 128
#define HH 64
#define IT 4          // i-tiles per block
#define NEGS 0.01f
#define DRN2 0.16000000000000003f   // f32(0.4*0.4 in double)
#define TWO_PI 6.2831854820251465f  // 2.0 * np.float32(np.pi)

// Scratch
__device__ float g_a1[BB * NN * 2];      // rotated coords after layer 1
__device__ float g_u2[BB * NN * HH];     // per-node u for layer 2
__device__ float g_v2[BB * NN * HH];     // per-node v for layer 2
__device__ float g_feat2[BB * NN * 66];  // [agg_m2[:64], rot2] per node

// ---------------------------------------------------------------------------
// Layer 1 (Df=1) fused with u2/v2 precompute. Block = (b, 4 i's), 256 thr.
// ---------------------------------------------------------------------------
__global__ void __launch_bounds__(256) k_layer1uv(
    const float* __restrict__ ang,
    const float* __restrict__ W00, const float* __restrict__ b00,
    const float* __restrict__ W01, const float* __restrict__ b01,
    const float* __restrict__ W10, const float* __restrict__ b10) {
  int b = blockIdx.y;
  int t = threadIdx.x;
  int sub = t >> 6, lt = t & 63;
  int i = blockIdx.x * IT + sub;

  __shared__ float ax[NN], ay[NN], rr[NN];
  __shared__ float cs[IT][NN], sn[IT][NN], wj[IT][NN];
  __shared__ float hsm[IT][HH], fsm[IT][HH];
  __shared__ float red[IT][2];

  if (t < NN) {
    float x = ang[(b * NN + t) * 2 + 0];
    float y = ang[(b * NN + t) * 2 + 1];
    ax[t] = x; ay[t] = y;
    rr[t] = sqrtf(x * x + y * y);
  }
  __syncthreads();

  float xi = ax[i], yi = ay[i];
  float r2i = xi * xi + yi * yi;

  float padj = 0.f;
#pragma unroll
  for (int jj = 0; jj < 2; ++jj) {
    int j = lt + jj * 64;
    float xj = ax[j], yj = ay[j];
    float dx = xi - xj, dy = yi - yj;
    float adj = (dx * dx + dy * dy <= DRN2) ? 1.f : 0.f;
    padj += adj;
    float inv = rsqrtf(r2i * (xj * xj + yj * yj));
    cs[sub][j] = (xi * xj + yi * yj) * inv;
    sn[sub][j] = (yi * xj - xi * yj) * inv;
    wj[sub][j] = adj;
  }
  for (int o = 16; o; o >>= 1) padj += __shfl_down_sync(0xffffffffu, padj, o);
  if ((lt & 31) == 0) red[sub][lt >> 5] = padj;
  __syncthreads();
  float invdeg = 1.f / (red[sub][0] + red[sub][1]);
  wj[sub][lt] *= invdeg;
  wj[sub][lt + 64] *= invdeg;
  __syncthreads();

  int h = lt;
  float ri = rr[i];
  float u  = ri * (W00[h] - W00[128 + h]) + b00[h];
  float vc = W00[64 + h] + W00[128 + h];
  float wc = W00[192 + h], ws = W00[256 + h];
  float acc = 0.f;
#pragma unroll 8
  for (int j = 0; j < NN; ++j) {
    float z = u + rr[j] * vc + cs[sub][j] * wc + sn[sub][j] * ws;
    float zl = (z >= 0.f) ? z : NEGS * z;
    acc += wj[sub][j] * zl;
  }
  hsm[sub][h] = acc;
  __syncthreads();

  // f1 = hsm @ W01[:, :64] + b01
  float dot = b01[h];
#pragma unroll 8
  for (int k = 0; k < HH; ++k) dot += hsm[sub][k] * W01[k * 65 + h];
  fsm[sub][h] = dot;

  if (lt == 0) {  // gamma + rotation
    float gam = b01[64];
#pragma unroll 8
    for (int k = 0; k < HH; ++k) gam += hsm[sub][k] * W01[k * 65 + 64];
    float a2 = TWO_PI * gam;
    float co = cosf(a2), si = sinf(a2);
    g_a1[(b * NN + i) * 2 + 0] = co * xi - si * yi;
    g_a1[(b * NN + i) * 2 + 1] = si * xi + co * yi;
  }
  __syncthreads();

  // u2 = f1 @ (W10[0:64]-W10[128:192]) + b10 ; v2 = f1 @ (W10[64:128]+W10[128:192])
  float u2 = b10[h], v2 = 0.f;
#pragma unroll 8
  for (int d = 0; d < HH; ++d) {
    float fd = fsm[sub][d];
    float wa = W10[d * HH + h];
    float wb = W10[(64 + d) * HH + h];
    float wd = W10[(128 + d) * HH + h];
    u2 += fd * (wa - wd);
    v2 += fd * (wb + wd);
  }
  g_u2[(b * NN + i) * HH + h] = u2;
  g_v2[(b * NN + i) * HH + h] = v2;
}

// ---------------------------------------------------------------------------
// Layer 2 (Df=64), v2 tile staged in smem. Block = (b, 4 i's), 256 thr.
// ---------------------------------------------------------------------------
__global__ void __launch_bounds__(256) k_layer2(
    const float* __restrict__ W10, const float* __restrict__ W11,
    const float* __restrict__ b11) {
  int b = blockIdx.y;
  int t = threadIdx.x;
  int sub = t >> 6, lt = t & 63;
  int i = blockIdx.x * IT + sub;

  __shared__ float ax[NN], ay[NN];
  __shared__ float vsm[NN * HH];          // 32 KB, shared across 4 i's
  __shared__ float cs[IT][NN], sn[IT][NN], wj[IT][NN];
  __shared__ float hsm[IT][HH];
  __shared__ float red[IT][2];

  if (t < NN) {
    ax[t] = g_a1[(b * NN + t) * 2 + 0];
    ay[t] = g_a1[(b * NN + t) * 2 + 1];
  }
  const float* vsrc = g_v2 + (size_t)b * NN * HH;
#pragma unroll
  for (int idx = t; idx < NN * HH; idx += 256) vsm[idx] = vsrc[idx];
  __syncthreads();

  float xi = ax[i], yi = ay[i];
  float r2i = xi * xi + yi * yi;

  float padj = 0.f;
#pragma unroll
  for (int jj = 0; jj < 2; ++jj) {
    int j = lt + jj * 64;
    float xj = ax[j], yj = ay[j];
    float dx = xi - xj, dy = yi - yj;
    float adj = (dx * dx + dy * dy <= DRN2) ? 1.f : 0.f;
    padj += adj;
    float inv = rsqrtf(r2i * (xj * xj + yj * yj));
    cs[sub][j] = (xi * xj + yi * yj) * inv;
    sn[sub][j] = (yi * xj - xi * yj) * inv;
    wj[sub][j] = adj;
  }
  for (int o = 16; o; o >>= 1) padj += __shfl_down_sync(0xffffffffu, padj, o);
  if ((lt & 31) == 0) red[sub][lt >> 5] = padj;
  __syncthreads();
  float invdeg = 1.f / (red[sub][0] + red[sub][1]);
  wj[sub][lt] *= invdeg;
  wj[sub][lt + 64] *= invdeg;
  __syncthreads();

  int h = lt;
  float u  = g_u2[(b * NN + i) * HH + h];
  float wc = W10[192 * HH + h], ws = W10[193 * HH + h];
  float acc = 0.f;
#pragma unroll 8
  for (int j = 0; j < NN; ++j) {
    float z = u + vsm[j * HH + h] + cs[sub][j] * wc + sn[sub][j] * ws;
    float zl = (z >= 0.f) ? z : NEGS * z;
    acc += wj[sub][j] * zl;
  }
  hsm[sub][h] = acc;
  __syncthreads();

  float dot = b11[h];
#pragma unroll 8
  for (int k = 0; k < HH; ++k) dot += hsm[sub][k] * W11[k * 65 + h];
  g_feat2[(b * NN + i) * 66 + h] = dot;

  if (lt == 0) {
    float gam = b11[64];
#pragma unroll 8
    for (int k = 0; k < HH; ++k) gam += hsm[sub][k] * W11[k * 65 + 64];
    float a2 = TWO_PI * gam;
    float co = cosf(a2), si = sinf(a2);
    g_feat2[(b * NN + i) * 66 + 64] = co * xi - si * yi;
    g_feat2[(b * NN + i) * 66 + 65] = si * xi + co * yi;
  }
}

// ---------------------------------------------------------------------------
// Readout: stage weighted feat2 tile into smem, column-sum, tiny MLP.
// ---------------------------------------------------------------------------
__global__ void __launch_bounds__(256) k_readout(
    const float* __restrict__ pt,
    const float* __restrict__ Wr0, const float* __restrict__ br0,
    const float* __restrict__ Wr1, const float* __restrict__ br1,
    const float* __restrict__ Wr2, const float* __restrict__ br2,
    float* __restrict__ out) {
  int b = blockIdx.x, t = threadIdx.x;
  __shared__ float ptn[NN];
  __shared__ float wf[NN * 66];   // weighted features, 33 KB
  __shared__ float g[66], h1[32], h2[32];
  __shared__ float red[4];

  if (t < NN) ptn[t] = pt[b * NN + t];
  __syncthreads();

  if (t < NN) {
    float s = ptn[t];
    for (int o = 16; o; o >>= 1) s += __shfl_down_sync(0xffffffffu, s, o);
    if ((t & 31) == 0) red[t >> 5] = s;
  }
  __syncthreads();
  float invs = 1.f / (red[0] + red[1] + red[2] + red[3]);

  // Stage w_n * feat2[n][c] (parallel loads, high MLP)
  const float* fsrc = g_feat2 + (size_t)b * NN * 66;
#pragma unroll
  for (int idx = t; idx < NN * 66; idx += 256) {
    int n = idx / 66;
    wf[idx] = (ptn[n] * invs) * fsrc[idx];
  }
  __syncthreads();

  if (t < 66) {
    float acc = 0.f;
#pragma unroll 8
    for (int n = 0; n < NN; ++n) acc += wf[n * 66 + t];
    g[t] = acc;
  }
  __syncthreads();

  if (t < 32) {
    float z = br0[t];
#pragma unroll 8
    for (int d = 0; d < 64; ++d) z += g[d] * Wr0[d * 32 + t];
    h1[t] = (z >= 0.f) ? z : NEGS * z;
  }
  __syncthreads();
  if (t < 32) {
    float z = br1[t];
#pragma unroll 8
    for (int d = 0; d < 32; ++d) z += h1[d] * Wr1[d * 32 + t];
    h2[t] = (z >= 0.f) ? z : NEGS * z;
  }
  __syncthreads();
  if (t == 0) {
    float z = br2[0];
#pragma unroll 8
    for (int d = 0; d < 32; ++d) z += h2[d] * Wr2[d];
    out[b * 3 + 0] = 1.f / (1.f + expf(-z));
    out[b * 3 + 1] = g[64];
    out[b * 3 + 2] = g[65];
  }
}

extern "C" void kernel_launch(void* const* d_in, const int* in_sizes, int n_in,
                              void* d_out, int out_size) {
  const float* pt  = (const float*)d_in[0];
  const float* ang = (const float*)d_in[1];
  const float* W00 = (const float*)d_in[2];
  const float* b00 = (const float*)d_in[3];
  const float* W01 = (const float*)d_in[4];
  const float* b01 = (const float*)d_in[5];
  const float* W10 = (const float*)d_in[6];
  const float* b10 = (const float*)d_in[7];
  const float* W11 = (const float*)d_in[8];
  const float* b11 = (const float*)d_in[9];
  const float* Wr0 = (const float*)d_in[10];
  const float* br0 = (const float*)d_in[11];
  const float* Wr1 = (const float*)d_in[12];
  const float* br1 = (const float*)d_in[13];
  const float* Wr2 = (const float*)d_in[14];
  const float* br2 = (const float*)d_in[15];
  float* out = (float*)d_out;

  dim3 grid(NN / IT, BB);
  k_layer1uv<<<grid, 256>>>(ang, W00, b00, W01, b01, W10, b10);
  k_layer2<<<grid, 256>>>(W10, W11, b11);
  k_readout<<<BB, 256>>>(pt, Wr0, br0, Wr1, br1, Wr2, br2, out);
}

// round 3
// speedup vs baseline: 1.3361x; 1.1988x over previous
#include <cuda_runtime.h>
#include <math.h>

#define BB 16
#define NN 128
#define HH 64
#define IT 4
#define NEGS 0.01f
#define DRN2 0.16000000000000003f   // f32(0.4*0.4 in double)
#define TWO_PI 6.2831854820251465f  // 2.0 * np.float32(np.pi)

// Scratch
__device__ float g_a1[BB * NN * 2];
__device__ float g_u2[BB * NN * HH];
__device__ float g_v2[BB * NN * HH];
__device__ float g_feat2[BB * NN * 66];
// Precombined weights
__device__ float g_Mu[HH * HH];   // W01[:, :64]^T-combined @ (W10[0:64]-W10[128:192])
__device__ float g_Mv[HH * HH];
__device__ float g_cu[HH];
__device__ float g_cv[HH];
__device__ float g_w1a[HH];       // W00[0]-W00[2]  (fi - (fj-fi) slots)
__device__ float g_w1b[HH];       // W00[1]+W00[2]

__device__ __forceinline__ float leaky(float z) {
  return fmaxf(z, 0.f) + NEGS * fminf(z, 0.f);
}

// ---------------------------------------------------------------------------
// Setup: precombine weights. 64 blocks x 64 threads.
// ---------------------------------------------------------------------------
__global__ void __launch_bounds__(64) k_setup(
    const float* __restrict__ W00,
    const float* __restrict__ W01, const float* __restrict__ b01,
    const float* __restrict__ W10, const float* __restrict__ b10) {
  int k = blockIdx.x, h = threadIdx.x;
  float mu = 0.f, mv = 0.f;
#pragma unroll 8
  for (int d = 0; d < HH; ++d) {
    float w01 = W01[k * 65 + d];
    float wa = W10[d * HH + h];
    float wb = W10[(64 + d) * HH + h];
    float wd = W10[(128 + d) * HH + h];
    mu = fmaf(w01, wa - wd, mu);
    mv = fmaf(w01, wb + wd, mv);
  }
  g_Mu[k * HH + h] = mu;
  g_Mv[k * HH + h] = mv;
  if (k == 0) {
    float cu = b10[h], cv = 0.f;
#pragma unroll 8
    for (int d = 0; d < HH; ++d) {
      float bd = b01[d];
      float wa = W10[d * HH + h];
      float wb = W10[(64 + d) * HH + h];
      float wd = W10[(128 + d) * HH + h];
      cu = fmaf(bd, wa - wd, cu);
      cv = fmaf(bd, wb + wd, cv);
    }
    g_cu[h] = cu;
    g_cv[h] = cv;
    g_w1a[h] = W00[h] - W00[128 + h];
    g_w1b[h] = W00[64 + h] + W00[128 + h];
  }
}

// ---------------------------------------------------------------------------
// Adjacency compaction helper lives inline in each layer kernel.
// Layer 1 (Df=1): sparse j-loop, then u2/v2 via Mu/Mv, gamma & rotation.
// ---------------------------------------------------------------------------
__global__ void __launch_bounds__(256) k_layer1(
    const float* __restrict__ ang,
    const float* __restrict__ W00, const float* __restrict__ b00,
    const float* __restrict__ W01, const float* __restrict__ b01) {
  int b = blockIdx.y;
  int t = threadIdx.x;
  int sub = t >> 6, lt = t & 63;
  int w = lt >> 5, lane = lt & 31;
  int i = blockIdx.x * IT + sub;

  __shared__ float ax[NN], ay[NN], rr[NN];
  __shared__ unsigned msk[IT][4];
  __shared__ float4 glist[IT][NN];
  __shared__ float hsm[IT][HH];
  __shared__ float red[IT][2];

  if (t < NN) {
    float2 a = ((const float2*)ang)[b * NN + t];
    ax[t] = a.x; ay[t] = a.y;
    rr[t] = sqrtf(a.x * a.x + a.y * a.y);
  }
  __syncthreads();

  float xi = ax[i], yi = ay[i];
  float r2i = xi * xi + yi * yi;

  int j0 = lt, j1 = lt + 64;
  float x0 = ax[j0], y0 = ay[j0], x1 = ax[j1], y1 = ay[j1];
  float d0x = xi - x0, d0y = yi - y0, d1x = xi - x1, d1y = yi - y1;
  bool a0 = (d0x * d0x + d0y * d0y) <= DRN2;
  bool a1 = (d1x * d1x + d1y * d1y) <= DRN2;
  unsigned m0 = __ballot_sync(0xffffffffu, a0);
  unsigned m1 = __ballot_sync(0xffffffffu, a1);
  if (lane == 0) { msk[sub][w] = m0; msk[sub][2 + w] = m1; }
  __syncthreads();

  unsigned M0 = msk[sub][0], M1 = msk[sub][1], M2 = msk[sub][2], M3 = msk[sub][3];
  int c0 = __popc(M0), c1 = __popc(M1), c2 = __popc(M2);
  int deg = c0 + c1 + c2 + __popc(M3);
  unsigned below = (1u << lane) - 1u;
  if (a0) {
    int base = (w == 0) ? 0 : c0;
    int pos = base + __popc((w == 0 ? M0 : M1) & below);
    float inv = rsqrtf(r2i * (x0 * x0 + y0 * y0));
    glist[sub][pos] = make_float4((xi * x0 + yi * y0) * inv,
                                  (yi * x0 - xi * y0) * inv, rr[j0], 0.f);
  }
  if (a1) {
    int base = c0 + c1 + ((w == 0) ? 0 : c2);
    int pos = base + __popc((w == 0 ? M2 : M3) & below);
    float inv = rsqrtf(r2i * (x1 * x1 + y1 * y1));
    glist[sub][pos] = make_float4((xi * x1 + yi * y1) * inv,
                                  (yi * x1 - xi * y1) * inv, rr[j1], 0.f);
  }
  __syncthreads();

  int h = lt;
  float u  = fmaf(rr[i], g_w1a[h], b00[h]);
  float vc = g_w1b[h];
  float wc = W00[192 + h], ws = W00[256 + h];
  float acc = 0.f;
  for (int q = 0; q < deg; ++q) {
    float4 g4 = glist[sub][q];
    float z = fmaf(g4.z, vc, u);
    z = fmaf(g4.x, wc, z);
    z = fmaf(g4.y, ws, z);
    acc += leaky(z);
  }
  float hval = acc * (1.f / (float)deg);
  hsm[sub][h] = hval;

  // gamma partial (own value, no sync needed yet)
  float p = hval * W01[h * 65 + 64];
  for (int o = 16; o; o >>= 1) p += __shfl_down_sync(0xffffffffu, p, o);
  if (lane == 0) red[sub][w] = p;
  __syncthreads();

  // u2 / v2 via precombined Mu, Mv
  float u2 = g_cu[h], v2 = g_cv[h];
#pragma unroll 8
  for (int k = 0; k < HH; ++k) {
    float hk = hsm[sub][k];
    u2 = fmaf(hk, g_Mu[k * HH + h], u2);
    v2 = fmaf(hk, g_Mv[k * HH + h], v2);
  }
  g_u2[(b * NN + i) * HH + h] = u2;
  g_v2[(b * NN + i) * HH + h] = v2;

  if (lt == 0) {
    float gam = red[sub][0] + red[sub][1] + b01[64];
    float a2 = TWO_PI * gam;
    float co = cosf(a2), si = sinf(a2);
    g_a1[(b * NN + i) * 2 + 0] = co * xi - si * yi;
    g_a1[(b * NN + i) * 2 + 1] = si * xi + co * yi;
  }
}

// ---------------------------------------------------------------------------
// Layer 2 (Df=64): sparse j-loop over staged v2 tile.
// ---------------------------------------------------------------------------
__global__ void __launch_bounds__(256) k_layer2(
    const float* __restrict__ W10, const float* __restrict__ W11,
    const float* __restrict__ b11) {
  int b = blockIdx.y;
  int t = threadIdx.x;
  int sub = t >> 6, lt = t & 63;
  int w = lt >> 5, lane = lt & 31;
  int i = blockIdx.x * IT + sub;

  __shared__ float ax[NN], ay[NN];
  __shared__ float vsm[NN * HH];
  __shared__ unsigned msk[IT][4];
  __shared__ float4 glist[IT][NN];
  __shared__ float hsm[IT][HH];
  __shared__ float red[IT][2];

  if (t < NN) {
    float2 a = ((const float2*)g_a1)[b * NN + t];
    ax[t] = a.x; ay[t] = a.y;
  }
  {
    const float4* vsrc = (const float4*)(g_v2 + (size_t)b * NN * HH);
#pragma unroll
    for (int idx = t; idx < NN * HH / 4; idx += 256)
      ((float4*)vsm)[idx] = vsrc[idx];
  }
  __syncthreads();

  float xi = ax[i], yi = ay[i];
  float r2i = xi * xi + yi * yi;

  int j0 = lt, j1 = lt + 64;
  float x0 = ax[j0], y0 = ay[j0], x1 = ax[j1], y1 = ay[j1];
  float d0x = xi - x0, d0y = yi - y0, d1x = xi - x1, d1y = yi - y1;
  bool a0 = (d0x * d0x + d0y * d0y) <= DRN2;
  bool a1 = (d1x * d1x + d1y * d1y) <= DRN2;
  unsigned m0 = __ballot_sync(0xffffffffu, a0);
  unsigned m1 = __ballot_sync(0xffffffffu, a1);
  if (lane == 0) { msk[sub][w] = m0; msk[sub][2 + w] = m1; }
  __syncthreads();

  unsigned M0 = msk[sub][0], M1 = msk[sub][1], M2 = msk[sub][2], M3 = msk[sub][3];
  int c0 = __popc(M0), c1 = __popc(M1), c2 = __popc(M2);
  int deg = c0 + c1 + c2 + __popc(M3);
  unsigned below = (1u << lane) - 1u;
  if (a0) {
    int base = (w == 0) ? 0 : c0;
    int pos = base + __popc((w == 0 ? M0 : M1) & below);
    float inv = rsqrtf(r2i * (x0 * x0 + y0 * y0));
    glist[sub][pos] = make_float4((xi * x0 + yi * y0) * inv,
                                  (yi * x0 - xi * y0) * inv,
                                  __int_as_float(j0 * HH), 0.f);
  }
  if (a1) {
    int base = c0 + c1 + ((w == 0) ? 0 : c2);
    int pos = base + __popc((w == 0 ? M2 : M3) & below);
    float inv = rsqrtf(r2i * (x1 * x1 + y1 * y1));
    glist[sub][pos] = make_float4((xi * x1 + yi * y1) * inv,
                                  (yi * x1 - xi * y1) * inv,
                                  __int_as_float(j1 * HH), 0.f);
  }
  __syncthreads();

  int h = lt;
  float u  = g_u2[(b * NN + i) * HH + h];
  float wc = W10[192 * HH + h], ws = W10[193 * HH + h];
  float acc = 0.f;
  for (int q = 0; q < deg; ++q) {
    float4 g4 = glist[sub][q];
    float z = u + vsm[__float_as_int(g4.z) + h];
    z = fmaf(g4.x, wc, z);
    z = fmaf(g4.y, ws, z);
    acc += leaky(z);
  }
  float hval = acc * (1.f / (float)deg);
  hsm[sub][h] = hval;

  float p = hval * W11[h * 65 + 64];
  for (int o = 16; o; o >>= 1) p += __shfl_down_sync(0xffffffffu, p, o);
  if (lane == 0) red[sub][w] = p;
  __syncthreads();

  float dot = b11[h];
#pragma unroll 8
  for (int k = 0; k < HH; ++k) dot = fmaf(hsm[sub][k], W11[k * 65 + h], dot);
  g_feat2[(b * NN + i) * 66 + h] = dot;

  if (lt == 0) {
    float gam = red[sub][0] + red[sub][1] + b11[64];
    float a2 = TWO_PI * gam;
    float co = cosf(a2), si = sinf(a2);
    g_feat2[(b * NN + i) * 66 + 64] = co * xi - si * yi;
    g_feat2[(b * NN + i) * 66 + 65] = si * xi + co * yi;
  }
}

// ---------------------------------------------------------------------------
// Readout
// ---------------------------------------------------------------------------
__global__ void __launch_bounds__(256) k_readout(
    const float* __restrict__ pt,
    const float* __restrict__ Wr0, const float* __restrict__ br0,
    const float* __restrict__ Wr1, const float* __restrict__ br1,
    const float* __restrict__ Wr2, const float* __restrict__ br2,
    float* __restrict__ out) {
  int b = blockIdx.x, t = threadIdx.x;
  __shared__ float ptn[NN];
  __shared__ float wf[NN * 66];
  __shared__ float g[66], h1[32], h2[32];
  __shared__ float red[4];

  if (t < NN) ptn[t] = pt[b * NN + t];
  __syncthreads();
  if (t < NN) {
    float s = ptn[t];
    for (int o = 16; o; o >>= 1) s += __shfl_down_sync(0xffffffffu, s, o);
    if ((t & 31) == 0) red[t >> 5] = s;
  }
  __syncthreads();
  float invs = 1.f / (red[0] + red[1] + red[2] + red[3]);

  const float* fsrc = g_feat2 + (size_t)b * NN * 66;
#pragma unroll
  for (int idx = t; idx < NN * 66; idx += 256) {
    int n = idx / 66;
    wf[idx] = (ptn[n] * invs) * fsrc[idx];
  }
  __syncthreads();

  if (t < 66) {
    float acc = 0.f;
#pragma unroll 8
    for (int n = 0; n < NN; ++n) acc += wf[n * 66 + t];
    g[t] = acc;
  }
  __syncthreads();

  if (t < 32) {
    float z = br0[t];
#pragma unroll 8
    for (int d = 0; d < 64; ++d) z = fmaf(g[d], Wr0[d * 32 + t], z);
    h1[t] = leaky(z);
  }
  __syncthreads();
  if (t < 32) {
    float z = br1[t];
#pragma unroll 8
    for (int d = 0; d < 32; ++d) z = fmaf(h1[d], Wr1[d * 32 + t], z);
    h2[t] = leaky(z);
  }
  __syncthreads();
  if (t == 0) {
    float z = br2[0];
#pragma unroll 8
    for (int d = 0; d < 32; ++d) z = fmaf(h2[d], Wr2[d], z);
    out[b * 3 + 0] = 1.f / (1.f + expf(-z));
    out[b * 3 + 1] = g[64];
    out[b * 3 + 2] = g[65];
  }
}

extern "C" void kernel_launch(void* const* d_in, const int* in_sizes, int n_in,
                              void* d_out, int out_size) {
  const float* pt  = (const float*)d_in[0];
  const float* ang = (const float*)d_in[1];
  const float* W00 = (const float*)d_in[2];
  const float* b00 = (const float*)d_in[3];
  const float* W01 = (const float*)d_in[4];
  const float* b01 = (const float*)d_in[5];
  const float* W10 = (const float*)d_in[6];
  const float* b10 = (const float*)d_in[7];
  const float* W11 = (const float*)d_in[8];
  const float* b11 = (const float*)d_in[9];
  const float* Wr0 = (const float*)d_in[10];
  const float* br0 = (const float*)d_in[11];
  const float* Wr1 = (const float*)d_in[12];
  const float* br1 = (const float*)d_in[13];
  const float* Wr2 = (const float*)d_in[14];
  const float* br2 = (const float*)d_in[15];
  float* out = (float*)d_out;

  dim3 grid(NN / IT, BB);
  k_setup<<<64, 64>>>(W00, W01, b01, W10, b10);
  k_layer1<<<grid, 256>>>(ang, W00, b00, W01, b01);
  k_layer2<<<grid, 256>>>(W10, W11, b11);
  k_readout<<<BB, 256>>>(pt, Wr0, br0, Wr1, br1, Wr2, br2, out);
}